// round 13
// baseline (speedup 1.0000x reference)
#include <cuda_runtime.h>
#include <stdint.h>

// BloomEmbedding: out[n, h*32 + j] = tables[h, hash(ids[n], 42+h), j]
// ids: [819200] int32, tables: [4, 1000000, 32] f32, out: [819200, 128] f32
//
// R13: strict phase separation. The single-launch phased kernel has ~1184
// blocks (148 SMs x 8) in flight, so ~37% of each phase straddles the phase
// boundary, where the active footprint is 2 tables = 143MB > 126MB L2 and
// repeat-capture degrades. Launch one kernel per table instead: the graph
// serializes them, each phase's footprint is strictly 71.5MB. Inner body is
// the measured-best R9 shape: staggered dual 4-id batches (8 independent
// LDG.128 gathers issued before the first store's scoreboard wait),
// __ldcg gathers, __stcs full-line evict-first stores, natural 38 regs.

#define TABLE_SIZE 1000000u
#define SEED 42u
#define BATCH 4
#define IDS_PER_THREAD 8   // two staggered batches of 4

__device__ __forceinline__ uint32_t hash_id(uint32_t id, uint32_t seed) {
    uint32_t x = id + seed;
    x ^= x >> 16;
    x *= 0x7FEB352Du;
    x ^= x >> 15;
    x *= 0x846CA68Bu;
    x ^= x >> 16;
    return x % TABLE_SIZE;
}

__global__ void __launch_bounds__(256)
bloom_embedding_phase_kernel(const int* __restrict__ ids,
                             const float4* __restrict__ tables,
                             float4* __restrict__ out,
                             int n_ids, int h) {
    const uint32_t seed = SEED + (uint32_t)h;
    const uint32_t base = (uint32_t)h * TABLE_SIZE;

    int t = blockIdx.x * blockDim.x + threadIdx.x;
    int j = t & 7;                               // float4 within the 32-float sub-row
    int g = t >> 3;                              // id-group index
    int n0 = g * IDS_PER_THREAD;                 // first id of this group (8-aligned)
    if (n0 >= n_ids) return;

    const uint32_t col = (uint32_t)(h * 8 + j);  // out float4 column for (h, j)

    if (n0 + IDS_PER_THREAD <= n_ids) {
        // ---- batch A: ids n0..n0+3 ----
        int4 idA = __ldg((const int4*)(ids + n0));
        uint32_t srcA[BATCH];
        srcA[0] = (base + hash_id((uint32_t)idA.x, seed)) * 8u + (uint32_t)j;
        srcA[1] = (base + hash_id((uint32_t)idA.y, seed)) * 8u + (uint32_t)j;
        srcA[2] = (base + hash_id((uint32_t)idA.z, seed)) * 8u + (uint32_t)j;
        srcA[3] = (base + hash_id((uint32_t)idA.w, seed)) * 8u + (uint32_t)j;
        float4 vA[BATCH];
        #pragma unroll
        for (int k = 0; k < BATCH; k++) vA[k] = __ldcg(tables + srcA[k]);

        // ---- batch B: ids n0+4..n0+7 (hash while A is in flight) ----
        int4 idB = __ldg((const int4*)(ids + n0 + 4));
        uint32_t srcB[BATCH];
        srcB[0] = (base + hash_id((uint32_t)idB.x, seed)) * 8u + (uint32_t)j;
        srcB[1] = (base + hash_id((uint32_t)idB.y, seed)) * 8u + (uint32_t)j;
        srcB[2] = (base + hash_id((uint32_t)idB.z, seed)) * 8u + (uint32_t)j;
        srcB[3] = (base + hash_id((uint32_t)idB.w, seed)) * 8u + (uint32_t)j;
        float4 vB[BATCH];
        #pragma unroll
        for (int k = 0; k < BATCH; k++) vB[k] = __ldcg(tables + srcB[k]);

        // ---- drain A, then B ----
        #pragma unroll
        for (int k = 0; k < BATCH; k++)
            __stcs(out + (size_t)(n0 + k) * 32u + col, vA[k]);
        #pragma unroll
        for (int k = 0; k < BATCH; k++)
            __stcs(out + (size_t)(n0 + 4 + k) * 32u + col, vB[k]);
    } else {
        for (int k = 0; k < IDS_PER_THREAD && n0 + k < n_ids; k++) {
            uint32_t id  = (uint32_t)__ldg(ids + n0 + k);
            uint32_t idx = hash_id(id, seed);
            float4 v = __ldcg(tables + (size_t)(base + idx) * 8u + (size_t)j);
            __stcs(out + (size_t)(n0 + k) * 32u + col, v);
        }
    }
}

extern "C" void kernel_launch(void* const* d_in, const int* in_sizes, int n_in,
                              void* d_out, int out_size) {
    const int*    ids    = (const int*)d_in[0];
    const float4* tables = (const float4*)d_in[1];
    float4*       out    = (float4*)d_out;

    int n_ids = in_sizes[0];                     // 819200
    // per phase: one thread per (8-id group, j): n_ids/8 groups * 8 threads
    long long per_phase = ((long long)n_ids + IDS_PER_THREAD - 1) / IDS_PER_THREAD * 8;
    int threads = 256;
    int blocks = (int)((per_phase + threads - 1) / threads);
    // one launch per table: graph serializes phases, so the active table
    // footprint never exceeds 71.5MB (vs 143MB in the boundary-overlap window
    // of the single-launch version).
    for (int h = 0; h < 4; h++)
        bloom_embedding_phase_kernel<<<blocks, threads>>>(ids, tables, out, n_ids, h);
}

// round 14
// speedup vs baseline: 1.0686x; 1.0686x over previous
#include <cuda_runtime.h>
#include <stdint.h>

// BloomEmbedding: out[n, h*32 + j] = tables[h, hash(ids[n], 42+h), j]
// ids: [819200] int32, tables: [4, 1000000, 32] f32, out: [819200, 128] f32
//
// FINAL (measured best: ~113us kernel / ~118.7us bench, 6.1 TB/s, rel_err 0):
//  - Single launch, table-phased via blockIdx.y = h (x-fastest dispatch =>
//    phases run ~sequentially): active table footprint 71.5MB < 126MB L2
//    captures intra-table hash-repeat reuse (DRAM traffic ~750 -> ~691MB,
//    the structural floor: 419MB irreducible writes + ~272MB gather reads).
//    Phase-boundary block overlap keeps the DRAM queue full between phases —
//    splitting into 4 launches (R13) regressed via pipeline drain/ramp.
//  - Staggered dual 4-id batches: 8 independent LDG.128 gathers issue before
//    the first store's scoreboard wait (MLP beyond the Little's-law knee).
//  - int4-vectorized id loads; __ldcg gathers (L2-only); __stcs full-128B-line
//    output stores (evict-first; output never re-read).
//  - Natural 38-reg allocation; forcing 32 regs (R10) spills and regresses.

#define TABLE_SIZE 1000000u
#define SEED 42u
#define BATCH 4
#define IDS_PER_THREAD 8   // two staggered batches of 4

__device__ __forceinline__ uint32_t hash_id(uint32_t id, uint32_t seed) {
    uint32_t x = id + seed;
    x ^= x >> 16;
    x *= 0x7FEB352Du;
    x ^= x >> 15;
    x *= 0x846CA68Bu;
    x ^= x >> 16;
    return x % TABLE_SIZE;
}

__global__ void __launch_bounds__(256)
bloom_embedding_kernel(const int* __restrict__ ids,
                       const float4* __restrict__ tables,
                       float4* __restrict__ out,
                       int n_ids) {
    const int h = blockIdx.y;                    // table phase 0..3
    const uint32_t seed = SEED + (uint32_t)h;
    const uint32_t base = (uint32_t)h * TABLE_SIZE;

    int t = blockIdx.x * blockDim.x + threadIdx.x;
    int j = t & 7;                               // float4 within the 32-float sub-row
    int g = t >> 3;                              // id-group index
    int n0 = g * IDS_PER_THREAD;                 // first id of this group (8-aligned)
    if (n0 >= n_ids) return;

    const uint32_t col = (uint32_t)(h * 8 + j);  // out float4 column for (h, j)

    if (n0 + IDS_PER_THREAD <= n_ids) {
        // ---- batch A: ids n0..n0+3 ----
        int4 idA = __ldg((const int4*)(ids + n0));
        uint32_t srcA[BATCH];
        srcA[0] = (base + hash_id((uint32_t)idA.x, seed)) * 8u + (uint32_t)j;
        srcA[1] = (base + hash_id((uint32_t)idA.y, seed)) * 8u + (uint32_t)j;
        srcA[2] = (base + hash_id((uint32_t)idA.z, seed)) * 8u + (uint32_t)j;
        srcA[3] = (base + hash_id((uint32_t)idA.w, seed)) * 8u + (uint32_t)j;
        float4 vA[BATCH];
        #pragma unroll
        for (int k = 0; k < BATCH; k++) vA[k] = __ldcg(tables + srcA[k]);

        // ---- batch B: ids n0+4..n0+7 (hash while A is in flight) ----
        int4 idB = __ldg((const int4*)(ids + n0 + 4));
        uint32_t srcB[BATCH];
        srcB[0] = (base + hash_id((uint32_t)idB.x, seed)) * 8u + (uint32_t)j;
        srcB[1] = (base + hash_id((uint32_t)idB.y, seed)) * 8u + (uint32_t)j;
        srcB[2] = (base + hash_id((uint32_t)idB.z, seed)) * 8u + (uint32_t)j;
        srcB[3] = (base + hash_id((uint32_t)idB.w, seed)) * 8u + (uint32_t)j;
        float4 vB[BATCH];
        #pragma unroll
        for (int k = 0; k < BATCH; k++) vB[k] = __ldcg(tables + srcB[k]);

        // ---- drain A, then B ----
        #pragma unroll
        for (int k = 0; k < BATCH; k++)
            __stcs(out + (size_t)(n0 + k) * 32u + col, vA[k]);
        #pragma unroll
        for (int k = 0; k < BATCH; k++)
            __stcs(out + (size_t)(n0 + 4 + k) * 32u + col, vB[k]);
    } else {
        for (int k = 0; k < IDS_PER_THREAD && n0 + k < n_ids; k++) {
            uint32_t id  = (uint32_t)__ldg(ids + n0 + k);
            uint32_t idx = hash_id(id, seed);
            float4 v = __ldcg(tables + (size_t)(base + idx) * 8u + (size_t)j);
            __stcs(out + (size_t)(n0 + k) * 32u + col, v);
        }
    }
}

extern "C" void kernel_launch(void* const* d_in, const int* in_sizes, int n_in,
                              void* d_out, int out_size) {
    const int*    ids    = (const int*)d_in[0];
    const float4* tables = (const float4*)d_in[1];
    float4*       out    = (float4*)d_out;

    int n_ids = in_sizes[0];                     // 819200
    // per phase: one thread per (8-id group, j): n_ids/8 groups * 8 threads
    long long per_phase = ((long long)n_ids + IDS_PER_THREAD - 1) / IDS_PER_THREAD * 8;
    int threads = 256;
    dim3 grid((unsigned)((per_phase + threads - 1) / threads), 4, 1);
    bloom_embedding_kernel<<<grid, threads>>>(ids, tables, out, n_ids);
}